// round 12
// baseline (speedup 1.0000x reference)
#include <cuda_runtime.h>
#include <cuda_bf16.h>
#include <math.h>
#include <stdint.h>

// ---------------- problem constants ----------------
#define BB     32
#define CC     64
#define FHH    80
#define FWW    200
#define SPP    36
#define LANES_ 64
#define PE_    78
#define RH_    10
#define RW_    25
#define NPOOL  250
#define KDIM   2304          // SPP * CC   (k = s*64 + c)
#define NROW   2048          // B * LANES
#define NSPLIT 12
#define KSPL   192           // KDIM / NSPLIT
#define NCHUNK 6             // KSPL / 32
#define RPADH  264           // bf16 r-stride in attn smem (528B rows)

// ---------------- device scratch ----------------
__device__ float g_xf[BB * CC * NPOOL];             // pooled features [b][c][r]
__device__ float g_W2t[KDIM * CC];                  // fused weight, k-major [k][o]
__device__ float g_b2[CC];
__device__ float g_roiT[(size_t)KDIM * NROW];       // roi, k-major [k][n]
__device__ float g_xp_part[NSPLIT][NROW * CC];
__device__ float g_gv[BB * LANES_ * CC];

__device__ __forceinline__ uint32_t smem_u32(const void* p) {
    uint32_t a;
    asm("{ .reg .u64 t; cvta.to.shared.u64 t, %1; cvt.u32.u64 %0, t; }"
        : "=r"(a) : "l"(p));
    return a;
}

// ---------------- pg part: TMA pool+gather (per channel-image) -------------
__device__ __forceinline__ void pg_body(
        const float* __restrict__ f, const float* __restrict__ prior,
        int c, int b, float* sm) {
    float* img = sm;                                   // [16000]
    unsigned int* xid = (unsigned int*)(sm + FHH * FWW); // [2304]
    unsigned long long* mbar =
        (unsigned long long*)(sm + FHH * FWW + SPP * LANES_);
    int tid = threadIdx.x;

    uint32_t mbar_a = smem_u32(mbar);
    uint32_t img_a  = smem_u32(img);

    if (tid == 0) {
        asm volatile("mbarrier.init.shared.b64 [%0], %1;"
                     :: "r"(mbar_a), "r"(1) : "memory");
    }
    __syncthreads();

    if (tid == 0) {
        const float* src = f + (size_t)(b * CC + c) * (FHH * FWW);
        asm volatile("mbarrier.arrive.expect_tx.shared.b64 _, [%0], %1;"
                     :: "r"(mbar_a), "r"(FHH * FWW * 4) : "memory");
        asm volatile(
            "cp.async.bulk.shared::cluster.global.mbarrier::complete_tx::bytes "
            "[%0], [%1], %2, [%3];"
            :: "r"(img_a), "l"(src), "r"(FHH * FWW * 4), "r"(mbar_a)
            : "memory");
    }

    for (int i = tid; i < SPP * LANES_; i += 256) {
        int sp = i >> 6, lane = i & 63;
        float xv = prior[(b * LANES_ + lane) * PE_ + 6 + 2 * sp] * 0.25f;
        xv = fminf(xv, 199.0f);
        unsigned int xf = (unsigned int)(int)floorf(xv);
        unsigned int xc = (unsigned int)(int)ceilf(xv);
        xid[i] = xf | (xc << 16);
    }

    asm volatile(
        "{\n\t"
        ".reg .pred P;\n\t"
        "W%=:\n\t"
        "mbarrier.try_wait.parity.shared.b64 P, [%0], 0;\n\t"
        "@!P bra W%=;\n\t"
        "}"
        :: "r"(mbar_a) : "memory");
    __syncthreads();

    if (tid < NPOOL) {
        int rh = tid / RW_, rw = tid % RW_;
        const float* base = img + rh * 8 * FWW + rw * 8;
        float s = 0.f;
        #pragma unroll
        for (int rr = 0; rr < 8; rr++) {
            float4 a = *(const float4*)(base + rr * FWW);
            float4 bq = *(const float4*)(base + rr * FWW + 4);
            s += a.x + a.y + a.z + a.w + bq.x + bq.y + bq.z + bq.w;
        }
        g_xf[(size_t)(b * CC + c) * NPOOL + tid] = s * (1.0f / 64.0f);
    }

    #pragma unroll
    for (int it = 0; it < 9; it++) {
        int i = tid + it * 256;
        int sp = i >> 6, lane = i & 63;
        float yv = 0.25f * (319.0f - (320.0f / 71.0f) * (float)(2 * sp));
        yv = fminf(yv, 79.0f);
        int yf = (int)floorf(yv);
        int yc = (int)ceilf(yv);
        unsigned int p = xid[i];
        int xf = (int)(p & 0xffffu), xc = (int)(p >> 16);
        const float* rA = img + yf * FWW;
        const float* rB = img + yc * FWW;
        float v = rA[xf] + rA[xc] + rB[xf] + rB[xc];
        g_roiT[(size_t)(sp * CC + c) * NROW + b * LANES_ + lane] = 0.25f * v;
    }
}

// ---------------- w2 part: fuse conv1d + fc into W2t / b2 ------------------
__device__ __forceinline__ void w2_body(
        const float* __restrict__ conv_w, const float* __restrict__ conv_b,
        const float* __restrict__ fc_w,   const float* __restrict__ fc_b,
        int o, int q, float* sm) {
    float* fcrow = sm;            // [2048]
    float* convs = sm + 2048;     // [5120]  [c2][c1l][k]
    float* bpart = sm + 7168;     // [64]
    int tid = threadIdx.x;

    for (int i = tid; i < 2048; i += 256) fcrow[i] = fc_w[o * 2048 + i];
    for (int i = tid; i < 5120; i += 256) {
        int c2 = i / 80, rem = i % 80;
        int c1l = rem / 5, k = rem % 5;
        convs[i] = conv_w[(c2 * CC + q * 16 + c1l) * 5 + k];
    }
    __syncthreads();

    for (int i = tid; i < 16 * SPP; i += 256) {
        int c1l = i / SPP, s = i % SPP;
        float acc = 0.f;
        for (int c2 = 0; c2 < CC; c2++) {
            const float* w5 = &convs[c2 * 80 + c1l * 5];
            const float* fr = &fcrow[c2 * 32];
            #pragma unroll
            for (int k = 0; k < 5; k++) {
                int p = s - k;
                if (p >= 0 && p < 32) acc += w5[k] * fr[p];
            }
        }
        g_W2t[(size_t)(s * CC + q * 16 + c1l) * CC + o] = acc;
    }

    if (q == 0) {
        if (tid < CC) {
            float s = 0.f;
            #pragma unroll
            for (int p = 0; p < 32; p++) s += fcrow[tid * 32 + p];
            bpart[tid] = s * conv_b[tid];
        }
        __syncthreads();
        if (tid == 0) {
            float s = fc_b[o];
            for (int j = 0; j < CC; j++) s += bpart[j];
            g_b2[o] = s;
        }
    }
}

// ---------------- K1: merged prep (w2 blocks first, then pg blocks) --------
__global__ void __launch_bounds__(256) prep_kernel(
        const float* __restrict__ f, const float* __restrict__ prior,
        const float* __restrict__ conv_w, const float* __restrict__ conv_b,
        const float* __restrict__ fc_w,   const float* __restrict__ fc_b) {
    extern __shared__ float sm[];
    int bid = blockIdx.x;
    if (bid < 256) {
        w2_body(conv_w, conv_b, fc_w, fc_b, bid >> 2, bid & 3, sm);
    } else {
        int idx = bid - 256;
        pg_body(f, prior, idx & 63, idx >> 6, sm);
    }
}

// ---------------- K2: tf32 tensor-core GEMM, K-split, double-buffered ------
__device__ __forceinline__ uint32_t f2tf32(float x) {
    uint32_t u;
    asm("cvt.rna.tf32.f32 %0, %1;" : "=r"(u) : "f"(x));
    return u;
}

__global__ void __launch_bounds__(256) gemm_kernel() {
    int mblk = blockIdx.x;
    int spl  = blockIdx.y;
    int tid = threadIdx.x;
    int wid = tid >> 5;
    int t = tid & 31;
    int row0 = mblk * 64;
    int k0 = spl * KSPL;

    int warp_m = (wid & 3) * 16;
    int warp_n = (wid >> 2) * 32;
    int g = t >> 2;
    int r = t & 3;

    __shared__ uint32_t As[2][32][72];
    __shared__ uint32_t Bs[2][32][72];

    int lk = tid >> 4, lq = tid & 15;

    float acc[4][4];
    #pragma unroll
    for (int j = 0; j < 4; j++)
        #pragma unroll
        for (int i = 0; i < 4; i++) acc[j][i] = 0.f;

    float4 ra0, ra1, rb0, rb1;
    {
        const float* srcA = g_roiT + (size_t)k0 * NROW + row0;
        const float* srcB = g_W2t + (size_t)k0 * CC;
        ra0 = *(const float4*)(srcA + (size_t)lk * NROW + lq * 4);
        ra1 = *(const float4*)(srcA + (size_t)(lk + 16) * NROW + lq * 4);
        rb0 = *(const float4*)(srcB + (size_t)lk * CC + lq * 4);
        rb1 = *(const float4*)(srcB + (size_t)(lk + 16) * CC + lq * 4);
        As[0][lk][lq * 4 + 0] = f2tf32(ra0.x); As[0][lk][lq * 4 + 1] = f2tf32(ra0.y);
        As[0][lk][lq * 4 + 2] = f2tf32(ra0.z); As[0][lk][lq * 4 + 3] = f2tf32(ra0.w);
        As[0][lk + 16][lq * 4 + 0] = f2tf32(ra1.x); As[0][lk + 16][lq * 4 + 1] = f2tf32(ra1.y);
        As[0][lk + 16][lq * 4 + 2] = f2tf32(ra1.z); As[0][lk + 16][lq * 4 + 3] = f2tf32(ra1.w);
        Bs[0][lk][lq * 4 + 0] = f2tf32(rb0.x); Bs[0][lk][lq * 4 + 1] = f2tf32(rb0.y);
        Bs[0][lk][lq * 4 + 2] = f2tf32(rb0.z); Bs[0][lk][lq * 4 + 3] = f2tf32(rb0.w);
        Bs[0][lk + 16][lq * 4 + 0] = f2tf32(rb1.x); Bs[0][lk + 16][lq * 4 + 1] = f2tf32(rb1.y);
        Bs[0][lk + 16][lq * 4 + 2] = f2tf32(rb1.z); Bs[0][lk + 16][lq * 4 + 3] = f2tf32(rb1.w);
    }
    __syncthreads();

    #pragma unroll
    for (int ci = 0; ci < NCHUNK; ci++) {
        int cur = ci & 1, nxt = cur ^ 1;
        if (ci + 1 < NCHUNK) {
            const float* srcA = g_roiT + (size_t)(k0 + (ci + 1) * 32) * NROW + row0;
            const float* srcB = g_W2t + (size_t)(k0 + (ci + 1) * 32) * CC;
            ra0 = *(const float4*)(srcA + (size_t)lk * NROW + lq * 4);
            ra1 = *(const float4*)(srcA + (size_t)(lk + 16) * NROW + lq * 4);
            rb0 = *(const float4*)(srcB + (size_t)lk * CC + lq * 4);
            rb1 = *(const float4*)(srcB + (size_t)(lk + 16) * CC + lq * 4);
        }
        #pragma unroll
        for (int ks = 0; ks < 32; ks += 8) {
            uint32_t a0 = As[cur][ks + r][warp_m + g];
            uint32_t a1 = As[cur][ks + r][warp_m + g + 8];
            uint32_t a2 = As[cur][ks + 4 + r][warp_m + g];
            uint32_t a3 = As[cur][ks + 4 + r][warp_m + g + 8];
            #pragma unroll
            for (int j = 0; j < 4; j++) {
                uint32_t b0 = Bs[cur][ks + r][warp_n + j * 8 + g];
                uint32_t b1 = Bs[cur][ks + 4 + r][warp_n + j * 8 + g];
                asm volatile(
                    "mma.sync.aligned.m16n8k8.row.col.f32.tf32.tf32.f32 "
                    "{%0,%1,%2,%3}, {%4,%5,%6,%7}, {%8,%9}, {%0,%1,%2,%3};"
                    : "+f"(acc[j][0]), "+f"(acc[j][1]),
                      "+f"(acc[j][2]), "+f"(acc[j][3])
                    : "r"(a0), "r"(a1), "r"(a2), "r"(a3),
                      "r"(b0), "r"(b1));
            }
        }
        if (ci + 1 < NCHUNK) {
            As[nxt][lk][lq * 4 + 0] = f2tf32(ra0.x); As[nxt][lk][lq * 4 + 1] = f2tf32(ra0.y);
            As[nxt][lk][lq * 4 + 2] = f2tf32(ra0.z); As[nxt][lk][lq * 4 + 3] = f2tf32(ra0.w);
            As[nxt][lk + 16][lq * 4 + 0] = f2tf32(ra1.x); As[nxt][lk + 16][lq * 4 + 1] = f2tf32(ra1.y);
            As[nxt][lk + 16][lq * 4 + 2] = f2tf32(ra1.z); As[nxt][lk + 16][lq * 4 + 3] = f2tf32(ra1.w);
            Bs[nxt][lk][lq * 4 + 0] = f2tf32(rb0.x); Bs[nxt][lk][lq * 4 + 1] = f2tf32(rb0.y);
            Bs[nxt][lk][lq * 4 + 2] = f2tf32(rb0.z); Bs[nxt][lk][lq * 4 + 3] = f2tf32(rb0.w);
            Bs[nxt][lk + 16][lq * 4 + 0] = f2tf32(rb1.x); Bs[nxt][lk + 16][lq * 4 + 1] = f2tf32(rb1.y);
            Bs[nxt][lk + 16][lq * 4 + 2] = f2tf32(rb1.z); Bs[nxt][lk + 16][lq * 4 + 3] = f2tf32(rb1.w);
            __syncthreads();
        }
    }

    float* outp = &g_xp_part[spl][0];
    #pragma unroll
    for (int j = 0; j < 4; j++) {
        int colb = warp_n + j * 8 + 2 * r;
        int rowa = row0 + warp_m + g;
        *(float2*)&outp[(size_t)rowa * CC + colb] =
            make_float2(acc[j][0], acc[j][1]);
        *(float2*)&outp[(size_t)(rowa + 8) * CC + colb] =
            make_float2(acc[j][2], acc[j][3]);
    }
}

// ---------------- K3: attention v3 (bf16 xfs, 44KB smem, 5 blocks/SM) ------
// block = (lq 0..7, b). 8 warps, one lane each: lane = lq*8 + w.
__global__ void __launch_bounds__(256) attn_kernel() {
    extern __shared__ float smf[];
    __nv_bfloat16* xfs = (__nv_bfloat16*)smf;        // [64][RPADH] bf16
    float* wbf = smf + (CC * RPADH) / 2;             // [8][260]
    float* xps = wbf + 8 * 260;                      // [8][64]

    int lq = blockIdx.x;                             // 0..7
    int b = blockIdx.y;
    int tid = threadIdx.x;
    int w = tid >> 5, t = tid & 31;
    int lane = lq * 8 + w;
    int n = b * LANES_ + lane;

    // load x_f (fp32 global -> bf16 smem), zero-pad r in [250, RPADH)
    {
        const float* src = &g_xf[(size_t)b * (CC * NPOOL)];
        for (int i = tid; i < CC * NPOOL; i += 256) {
            int c = i / NPOOL, r = i % NPOOL;
            xfs[c * RPADH + r] = __float2bfloat16_rn(src[i]);
        }
        for (int i = tid; i < CC * (RPADH - NPOOL); i += 256) {
            int c = i / (RPADH - NPOOL), r = NPOOL + i % (RPADH - NPOOL);
            xfs[c * RPADH + r] = __float2bfloat16_rn(0.f);
        }
    }
    // x_p: reduce split partials + bias
    {
        const float* bp = &g_xp_part[0][0];
        #pragma unroll 2
        for (int jj = 0; jj < 2; jj++) {
            int o = t + jj * 32;
            float s = g_b2[o];
            #pragma unroll
            for (int sp_ = 0; sp_ < NSPLIT; sp_++)
                s += bp[(size_t)sp_ * (NROW * CC) + n * CC + o];
            xps[w * CC + o] = s;
        }
    }
    __syncthreads();

    // scores: thread t owns r = 8t..8t+7
    float sc[8];
    #pragma unroll
    for (int j = 0; j < 8; j++) sc[j] = 0.f;
    {
        const float* xp = &xps[w * CC];
        #pragma unroll 4
        for (int c = 0; c < CC; c++) {
            float xv = xp[c];
            uint4 v = ((const uint4*)(xfs + c * RPADH))[t];
            float2 f0 = __bfloat1622float2(*(__nv_bfloat162*)&v.x);
            float2 f1 = __bfloat1622float2(*(__nv_bfloat162*)&v.y);
            float2 f2 = __bfloat1622float2(*(__nv_bfloat162*)&v.z);
            float2 f3 = __bfloat1622float2(*(__nv_bfloat162*)&v.w);
            sc[0] += xv * f0.x; sc[1] += xv * f0.y;
            sc[2] += xv * f1.x; sc[3] += xv * f1.y;
            sc[4] += xv * f2.x; sc[5] += xv * f2.y;
            sc[6] += xv * f3.x; sc[7] += xv * f3.y;
        }
    }
    float mx = -1e30f;
    #pragma unroll
    for (int j = 0; j < 8; j++) {
        int r = 8 * t + j;
        sc[j] = (r < NPOOL) ? sc[j] * 0.125f : -1e30f;
        mx = fmaxf(mx, sc[j]);
    }
    #pragma unroll
    for (int off = 16; off > 0; off >>= 1)
        mx = fmaxf(mx, __shfl_xor_sync(0xffffffffu, mx, off));
    float sum = 0.f;
    #pragma unroll
    for (int j = 0; j < 8; j++) { sc[j] = __expf(sc[j] - mx); sum += sc[j]; }
    #pragma unroll
    for (int off = 16; off > 0; off >>= 1)
        sum += __shfl_xor_sync(0xffffffffu, sum, off);
    float inv = 1.0f / sum;
    {
        float* wr = &wbf[w * 260];
        *(float4*)&wr[8 * t] =
            make_float4(sc[0] * inv, sc[1] * inv, sc[2] * inv, sc[3] * inv);
        *(float4*)&wr[8 * t + 4] =
            make_float4(sc[4] * inv, sc[5] * inv, sc[6] * inv, sc[7] * inv);
    }
    __syncwarp();

    // g[c] = sum_r w[r]*xf[c][r]; thread owns c = t, t+32
    {
        const float* wr = &wbf[w * 260];
        float a0 = 0.f, a1 = 0.f;
        #pragma unroll 4
        for (int q = 0; q < 32; q++) {
            float4 w0 = *(const float4*)&wr[8 * q];
            float4 w1 = *(const float4*)&wr[8 * q + 4];
            uint4 v0 = ((const uint4*)(xfs + t * RPADH))[q];
            uint4 v1 = ((const uint4*)(xfs + (t + 32) * RPADH))[q];
            float2 p;
            p = __bfloat1622float2(*(__nv_bfloat162*)&v0.x); a0 += w0.x * p.x + w0.y * p.y;
            p = __bfloat1622float2(*(__nv_bfloat162*)&v0.y); a0 += w0.z * p.x + w0.w * p.y;
            p = __bfloat1622float2(*(__nv_bfloat162*)&v0.z); a0 += w1.x * p.x + w1.y * p.y;
            p = __bfloat1622float2(*(__nv_bfloat162*)&v0.w); a0 += w1.z * p.x + w1.w * p.y;
            p = __bfloat1622float2(*(__nv_bfloat162*)&v1.x); a1 += w0.x * p.x + w0.y * p.y;
            p = __bfloat1622float2(*(__nv_bfloat162*)&v1.y); a1 += w0.z * p.x + w0.w * p.y;
            p = __bfloat1622float2(*(__nv_bfloat162*)&v1.z); a1 += w1.x * p.x + w1.y * p.y;
            p = __bfloat1622float2(*(__nv_bfloat162*)&v1.w); a1 += w1.z * p.x + w1.w * p.y;
        }
        g_gv[b * (LANES_ * CC) + lane * CC + t] = a0;
        g_gv[b * (LANES_ * CC) + lane * CC + t + 32] = a1;
    }
}

// ---------------- K4: conv1x1 + relu + broadcast-add prior ----------------
__global__ void final_kernel(const float* __restrict__ w1x1,
                             const float* __restrict__ b1x1,
                             const float* __restrict__ prior,
                             float* __restrict__ out) {
    int og = blockIdx.x;
    int b = blockIdx.y;
    int tid = threadIdx.x;
    int w = tid >> 5, t = tid & 31;

    __shared__ float gvs[4096];
    __shared__ float vals[8];
    for (int i = tid; i < 4096; i += 256) gvs[i] = g_gv[b * 4096 + i];
    __syncthreads();

    int o = og * 8 + w;
    const float* wrow = w1x1 + (size_t)o * 4096;
    float s = 0.f;
    for (int j = t * 4; j < 4096; j += 128) {
        float4 wv = *(const float4*)&wrow[j];
        float4 gv = *(const float4*)&gvs[j];
        s += wv.x * gv.x + wv.y * gv.y + wv.z * gv.z + wv.w * gv.w;
    }
    #pragma unroll
    for (int off = 16; off > 0; off >>= 1)
        s += __shfl_xor_sync(0xffffffffu, s, off);
    if (t == 0) vals[w] = fmaxf(s + b1x1[o], 0.f);
    __syncthreads();

    for (int i = tid; i < 8 * PE_; i += 256) {
        int oo = i / PE_, e = i % PE_;
        int oabs = og * 8 + oo;
        int idx = b * (CC * PE_) + oabs * PE_ + e;
        out[idx] = vals[oo] + prior[idx];
    }
}

// ---------------- launch ----------------
extern "C" void kernel_launch(void* const* d_in, const int* in_sizes, int n_in,
                              void* d_out, int out_size) {
    const float* feat    = (const float*)d_in[0];
    const float* prior   = (const float*)d_in[1];
    const float* conv_w  = (const float*)d_in[2];
    const float* conv_b  = (const float*)d_in[3];
    const float* fc_w    = (const float*)d_in[4];
    const float* fc_b    = (const float*)d_in[5];
    const float* w1x1    = (const float*)d_in[6];
    const float* b1x1    = (const float*)d_in[7];
    float* out = (float*)d_out;

    const int prep_smem = (FHH * FWW) * 4 + (SPP * LANES_) * 4 + 16;
    const int attn_smem = (CC * RPADH) * 2 + (8 * 260 + 8 * CC) * 4;
    cudaFuncSetAttribute(prep_kernel,
                         cudaFuncAttributeMaxDynamicSharedMemorySize, prep_smem);
    cudaFuncSetAttribute(attn_kernel,
                         cudaFuncAttributeMaxDynamicSharedMemorySize, attn_smem);

    prep_kernel<<<256 + CC * BB, 256, prep_smem>>>(feat, prior, conv_w, conv_b,
                                                   fc_w, fc_b);
    gemm_kernel<<<dim3(32, NSPLIT), 256>>>();
    attn_kernel<<<dim3(8, BB), 256, attn_smem>>>();
    final_kernel<<<dim3(8, BB), 256>>>(w1x1, b1x1, prior, out);
}

// round 13
// speedup vs baseline: 1.0050x; 1.0050x over previous
#include <cuda_runtime.h>
#include <cuda_bf16.h>
#include <math.h>
#include <stdint.h>

// ---------------- problem constants ----------------
#define BB     32
#define CC     64
#define FHH    80
#define FWW    200
#define SPP    36
#define LANES_ 64
#define PE_    78
#define RH_    10
#define RW_    25
#define NPOOL  250
#define KDIM   2304          // SPP * CC   (k = s*64 + c)
#define NROW   2048          // B * LANES
#define NSPLIT 12
#define KSPL   192           // KDIM / NSPLIT
#define NCHUNK 6             // KSPL / 32
#define RPADH  264           // bf16 r-stride in attn smem (528B rows)

// ---------------- device scratch ----------------
__device__ float g_xf[BB * CC * NPOOL];             // pooled features [b][c][r]
__device__ float g_W2t[KDIM * CC];                  // fused weight, k-major [k][o]
__device__ float g_b2[CC];
__device__ float g_roiT[(size_t)KDIM * NROW];       // roi, k-major [k][n]
__device__ float g_xp_part[NSPLIT][NROW * CC];
__device__ float g_gv[BB * LANES_ * CC];

__device__ __forceinline__ uint32_t smem_u32(const void* p) {
    uint32_t a;
    asm("{ .reg .u64 t; cvta.to.shared.u64 t, %1; cvt.u32.u64 %0, t; }"
        : "=r"(a) : "l"(p));
    return a;
}

// ---------------- pg part: TMA pool+gather (per channel-image) -------------
__device__ __forceinline__ void pg_body(
        const float* __restrict__ f, const float* __restrict__ prior,
        int c, int b, float* sm) {
    float* img = sm;                                   // [16000]
    unsigned int* xid = (unsigned int*)(sm + FHH * FWW); // [2304]
    unsigned long long* mbar =
        (unsigned long long*)(sm + FHH * FWW + SPP * LANES_);
    int tid = threadIdx.x;

    uint32_t mbar_a = smem_u32(mbar);
    uint32_t img_a  = smem_u32(img);

    if (tid == 0) {
        asm volatile("mbarrier.init.shared.b64 [%0], %1;"
                     :: "r"(mbar_a), "r"(1) : "memory");
    }
    __syncthreads();

    if (tid == 0) {
        const float* src = f + (size_t)(b * CC + c) * (FHH * FWW);
        asm volatile("mbarrier.arrive.expect_tx.shared.b64 _, [%0], %1;"
                     :: "r"(mbar_a), "r"(FHH * FWW * 4) : "memory");
        asm volatile(
            "cp.async.bulk.shared::cluster.global.mbarrier::complete_tx::bytes "
            "[%0], [%1], %2, [%3];"
            :: "r"(img_a), "l"(src), "r"(FHH * FWW * 4), "r"(mbar_a)
            : "memory");
    }

    for (int i = tid; i < SPP * LANES_; i += 256) {
        int sp = i >> 6, lane = i & 63;
        float xv = prior[(b * LANES_ + lane) * PE_ + 6 + 2 * sp] * 0.25f;
        xv = fminf(xv, 199.0f);
        unsigned int xf = (unsigned int)(int)floorf(xv);
        unsigned int xc = (unsigned int)(int)ceilf(xv);
        xid[i] = xf | (xc << 16);
    }

    asm volatile(
        "{\n\t"
        ".reg .pred P;\n\t"
        "W%=:\n\t"
        "mbarrier.try_wait.parity.shared.b64 P, [%0], 0;\n\t"
        "@!P bra W%=;\n\t"
        "}"
        :: "r"(mbar_a) : "memory");
    __syncthreads();

    if (tid < NPOOL) {
        int rh = tid / RW_, rw = tid % RW_;
        const float* base = img + rh * 8 * FWW + rw * 8;
        float s = 0.f;
        #pragma unroll
        for (int rr = 0; rr < 8; rr++) {
            float4 a = *(const float4*)(base + rr * FWW);
            float4 bq = *(const float4*)(base + rr * FWW + 4);
            s += a.x + a.y + a.z + a.w + bq.x + bq.y + bq.z + bq.w;
        }
        g_xf[(size_t)(b * CC + c) * NPOOL + tid] = s * (1.0f / 64.0f);
    }

    #pragma unroll
    for (int it = 0; it < 9; it++) {
        int i = tid + it * 256;
        int sp = i >> 6, lane = i & 63;
        float yv = 0.25f * (319.0f - (320.0f / 71.0f) * (float)(2 * sp));
        yv = fminf(yv, 79.0f);
        int yf = (int)floorf(yv);
        int yc = (int)ceilf(yv);
        unsigned int p = xid[i];
        int xf = (int)(p & 0xffffu), xc = (int)(p >> 16);
        const float* rA = img + yf * FWW;
        const float* rB = img + yc * FWW;
        float v = rA[xf] + rA[xc] + rB[xf] + rB[xc];
        g_roiT[(size_t)(sp * CC + c) * NROW + b * LANES_ + lane] = 0.25f * v;
    }
}

// ---------------- w2 part: fuse conv1d + fc into W2t / b2 ------------------
__device__ __forceinline__ void w2_body(
        const float* __restrict__ conv_w, const float* __restrict__ conv_b,
        const float* __restrict__ fc_w,   const float* __restrict__ fc_b,
        int o, int q, float* sm) {
    float* fcrow = sm;            // [2048]
    float* convs = sm + 2048;     // [5120]  [c2][c1l][k]
    float* bpart = sm + 7168;     // [64]
    int tid = threadIdx.x;

    for (int i = tid; i < 2048; i += 256) fcrow[i] = fc_w[o * 2048 + i];
    for (int i = tid; i < 5120; i += 256) {
        int c2 = i / 80, rem = i % 80;
        int c1l = rem / 5, k = rem % 5;
        convs[i] = conv_w[(c2 * CC + q * 16 + c1l) * 5 + k];
    }
    __syncthreads();

    for (int i = tid; i < 16 * SPP; i += 256) {
        int c1l = i / SPP, s = i % SPP;
        float acc = 0.f;
        for (int c2 = 0; c2 < CC; c2++) {
            const float* w5 = &convs[c2 * 80 + c1l * 5];
            const float* fr = &fcrow[c2 * 32];
            #pragma unroll
            for (int k = 0; k < 5; k++) {
                int p = s - k;
                if (p >= 0 && p < 32) acc += w5[k] * fr[p];
            }
        }
        g_W2t[(size_t)(s * CC + q * 16 + c1l) * CC + o] = acc;
    }

    if (q == 0) {
        if (tid < CC) {
            float s = 0.f;
            #pragma unroll
            for (int p = 0; p < 32; p++) s += fcrow[tid * 32 + p];
            bpart[tid] = s * conv_b[tid];
        }
        __syncthreads();
        if (tid == 0) {
            float s = fc_b[o];
            for (int j = 0; j < CC; j++) s += bpart[j];
            g_b2[o] = s;
        }
    }
}

// ---------------- K1: merged prep (w2 blocks first, then pg blocks) --------
__global__ void __launch_bounds__(256) prep_kernel(
        const float* __restrict__ f, const float* __restrict__ prior,
        const float* __restrict__ conv_w, const float* __restrict__ conv_b,
        const float* __restrict__ fc_w,   const float* __restrict__ fc_b) {
    extern __shared__ float sm[];
    int bid = blockIdx.x;
    if (bid < 256) {
        w2_body(conv_w, conv_b, fc_w, fc_b, bid >> 2, bid & 3, sm);
    } else {
        int idx = bid - 256;
        pg_body(f, prior, idx & 63, idx >> 6, sm);
    }
}

// ---------------- K2: tf32 tensor-core GEMM, K-split, double-buffered ------
__device__ __forceinline__ uint32_t f2tf32(float x) {
    uint32_t u;
    asm("cvt.rna.tf32.f32 %0, %1;" : "=r"(u) : "f"(x));
    return u;
}

__global__ void __launch_bounds__(256) gemm_kernel() {
    int mblk = blockIdx.x;
    int spl  = blockIdx.y;
    int tid = threadIdx.x;
    int wid = tid >> 5;
    int t = tid & 31;
    int row0 = mblk * 64;
    int k0 = spl * KSPL;

    int warp_m = (wid & 3) * 16;
    int warp_n = (wid >> 2) * 32;
    int g = t >> 2;
    int r = t & 3;

    __shared__ uint32_t As[2][32][72];
    __shared__ uint32_t Bs[2][32][72];

    int lk = tid >> 4, lq = tid & 15;

    float acc[4][4];
    #pragma unroll
    for (int j = 0; j < 4; j++)
        #pragma unroll
        for (int i = 0; i < 4; i++) acc[j][i] = 0.f;

    float4 ra0, ra1, rb0, rb1;
    {
        const float* srcA = g_roiT + (size_t)k0 * NROW + row0;
        const float* srcB = g_W2t + (size_t)k0 * CC;
        ra0 = *(const float4*)(srcA + (size_t)lk * NROW + lq * 4);
        ra1 = *(const float4*)(srcA + (size_t)(lk + 16) * NROW + lq * 4);
        rb0 = *(const float4*)(srcB + (size_t)lk * CC + lq * 4);
        rb1 = *(const float4*)(srcB + (size_t)(lk + 16) * CC + lq * 4);
        As[0][lk][lq * 4 + 0] = f2tf32(ra0.x); As[0][lk][lq * 4 + 1] = f2tf32(ra0.y);
        As[0][lk][lq * 4 + 2] = f2tf32(ra0.z); As[0][lk][lq * 4 + 3] = f2tf32(ra0.w);
        As[0][lk + 16][lq * 4 + 0] = f2tf32(ra1.x); As[0][lk + 16][lq * 4 + 1] = f2tf32(ra1.y);
        As[0][lk + 16][lq * 4 + 2] = f2tf32(ra1.z); As[0][lk + 16][lq * 4 + 3] = f2tf32(ra1.w);
        Bs[0][lk][lq * 4 + 0] = f2tf32(rb0.x); Bs[0][lk][lq * 4 + 1] = f2tf32(rb0.y);
        Bs[0][lk][lq * 4 + 2] = f2tf32(rb0.z); Bs[0][lk][lq * 4 + 3] = f2tf32(rb0.w);
        Bs[0][lk + 16][lq * 4 + 0] = f2tf32(rb1.x); Bs[0][lk + 16][lq * 4 + 1] = f2tf32(rb1.y);
        Bs[0][lk + 16][lq * 4 + 2] = f2tf32(rb1.z); Bs[0][lk + 16][lq * 4 + 3] = f2tf32(rb1.w);
    }
    __syncthreads();

    #pragma unroll
    for (int ci = 0; ci < NCHUNK; ci++) {
        int cur = ci & 1, nxt = cur ^ 1;
        if (ci + 1 < NCHUNK) {
            const float* srcA = g_roiT + (size_t)(k0 + (ci + 1) * 32) * NROW + row0;
            const float* srcB = g_W2t + (size_t)(k0 + (ci + 1) * 32) * CC;
            ra0 = *(const float4*)(srcA + (size_t)lk * NROW + lq * 4);
            ra1 = *(const float4*)(srcA + (size_t)(lk + 16) * NROW + lq * 4);
            rb0 = *(const float4*)(srcB + (size_t)lk * CC + lq * 4);
            rb1 = *(const float4*)(srcB + (size_t)(lk + 16) * CC + lq * 4);
        }
        #pragma unroll
        for (int ks = 0; ks < 32; ks += 8) {
            uint32_t a0 = As[cur][ks + r][warp_m + g];
            uint32_t a1 = As[cur][ks + r][warp_m + g + 8];
            uint32_t a2 = As[cur][ks + 4 + r][warp_m + g];
            uint32_t a3 = As[cur][ks + 4 + r][warp_m + g + 8];
            #pragma unroll
            for (int j = 0; j < 4; j++) {
                uint32_t b0 = Bs[cur][ks + r][warp_n + j * 8 + g];
                uint32_t b1 = Bs[cur][ks + 4 + r][warp_n + j * 8 + g];
                asm volatile(
                    "mma.sync.aligned.m16n8k8.row.col.f32.tf32.tf32.f32 "
                    "{%0,%1,%2,%3}, {%4,%5,%6,%7}, {%8,%9}, {%0,%1,%2,%3};"
                    : "+f"(acc[j][0]), "+f"(acc[j][1]),
                      "+f"(acc[j][2]), "+f"(acc[j][3])
                    : "r"(a0), "r"(a1), "r"(a2), "r"(a3),
                      "r"(b0), "r"(b1));
            }
        }
        if (ci + 1 < NCHUNK) {
            As[nxt][lk][lq * 4 + 0] = f2tf32(ra0.x); As[nxt][lk][lq * 4 + 1] = f2tf32(ra0.y);
            As[nxt][lk][lq * 4 + 2] = f2tf32(ra0.z); As[nxt][lk][lq * 4 + 3] = f2tf32(ra0.w);
            As[nxt][lk + 16][lq * 4 + 0] = f2tf32(ra1.x); As[nxt][lk + 16][lq * 4 + 1] = f2tf32(ra1.y);
            As[nxt][lk + 16][lq * 4 + 2] = f2tf32(ra1.z); As[nxt][lk + 16][lq * 4 + 3] = f2tf32(ra1.w);
            Bs[nxt][lk][lq * 4 + 0] = f2tf32(rb0.x); Bs[nxt][lk][lq * 4 + 1] = f2tf32(rb0.y);
            Bs[nxt][lk][lq * 4 + 2] = f2tf32(rb0.z); Bs[nxt][lk][lq * 4 + 3] = f2tf32(rb0.w);
            Bs[nxt][lk + 16][lq * 4 + 0] = f2tf32(rb1.x); Bs[nxt][lk + 16][lq * 4 + 1] = f2tf32(rb1.y);
            Bs[nxt][lk + 16][lq * 4 + 2] = f2tf32(rb1.z); Bs[nxt][lk + 16][lq * 4 + 3] = f2tf32(rb1.w);
            __syncthreads();
        }
    }

    float* outp = &g_xp_part[spl][0];
    #pragma unroll
    for (int j = 0; j < 4; j++) {
        int colb = warp_n + j * 8 + 2 * r;
        int rowa = row0 + warp_m + g;
        *(float2*)&outp[(size_t)rowa * CC + colb] =
            make_float2(acc[j][0], acc[j][1]);
        *(float2*)&outp[(size_t)(rowa + 8) * CC + colb] =
            make_float2(acc[j][2], acc[j][3]);
    }
}

// ---------------- K3: attention v3 (bf16 xfs, 44KB smem, 5 blocks/SM) ------
// block = (lq 0..7, b). 8 warps, one lane each: lane = lq*8 + w.
__global__ void __launch_bounds__(256) attn_kernel() {
    extern __shared__ float smf[];
    __nv_bfloat16* xfs = (__nv_bfloat16*)smf;        // [64][RPADH] bf16
    float* wbf = smf + (CC * RPADH) / 2;             // [8][260]
    float* xps = wbf + 8 * 260;                      // [8][64]

    int lq = blockIdx.x;                             // 0..7
    int b = blockIdx.y;
    int tid = threadIdx.x;
    int w = tid >> 5, t = tid & 31;
    int lane = lq * 8 + w;
    int n = b * LANES_ + lane;

    // load x_f (fp32 global -> bf16 smem), zero-pad r in [250, RPADH)
    {
        const float* src = &g_xf[(size_t)b * (CC * NPOOL)];
        for (int i = tid; i < CC * NPOOL; i += 256) {
            int c = i / NPOOL, r = i % NPOOL;
            xfs[c * RPADH + r] = __float2bfloat16_rn(src[i]);
        }
        for (int i = tid; i < CC * (RPADH - NPOOL); i += 256) {
            int c = i / (RPADH - NPOOL), r = NPOOL + i % (RPADH - NPOOL);
            xfs[c * RPADH + r] = __float2bfloat16_rn(0.f);
        }
    }
    // x_p: reduce split partials + bias
    {
        const float* bp = &g_xp_part[0][0];
        #pragma unroll 2
        for (int jj = 0; jj < 2; jj++) {
            int o = t + jj * 32;
            float s = g_b2[o];
            #pragma unroll
            for (int sp_ = 0; sp_ < NSPLIT; sp_++)
                s += bp[(size_t)sp_ * (NROW * CC) + n * CC + o];
            xps[w * CC + o] = s;
        }
    }
    __syncthreads();

    // scores: thread t owns r = 8t..8t+7
    float sc[8];
    #pragma unroll
    for (int j = 0; j < 8; j++) sc[j] = 0.f;
    {
        const float* xp = &xps[w * CC];
        #pragma unroll 4
        for (int c = 0; c < CC; c++) {
            float xv = xp[c];
            uint4 v = ((const uint4*)(xfs + c * RPADH))[t];
            float2 f0 = __bfloat1622float2(*(__nv_bfloat162*)&v.x);
            float2 f1 = __bfloat1622float2(*(__nv_bfloat162*)&v.y);
            float2 f2 = __bfloat1622float2(*(__nv_bfloat162*)&v.z);
            float2 f3 = __bfloat1622float2(*(__nv_bfloat162*)&v.w);
            sc[0] += xv * f0.x; sc[1] += xv * f0.y;
            sc[2] += xv * f1.x; sc[3] += xv * f1.y;
            sc[4] += xv * f2.x; sc[5] += xv * f2.y;
            sc[6] += xv * f3.x; sc[7] += xv * f3.y;
        }
    }
    float mx = -1e30f;
    #pragma unroll
    for (int j = 0; j < 8; j++) {
        int r = 8 * t + j;
        sc[j] = (r < NPOOL) ? sc[j] * 0.125f : -1e30f;
        mx = fmaxf(mx, sc[j]);
    }
    #pragma unroll
    for (int off = 16; off > 0; off >>= 1)
        mx = fmaxf(mx, __shfl_xor_sync(0xffffffffu, mx, off));
    float sum = 0.f;
    #pragma unroll
    for (int j = 0; j < 8; j++) { sc[j] = __expf(sc[j] - mx); sum += sc[j]; }
    #pragma unroll
    for (int off = 16; off > 0; off >>= 1)
        sum += __shfl_xor_sync(0xffffffffu, sum, off);
    float inv = 1.0f / sum;
    {
        float* wr = &wbf[w * 260];
        *(float4*)&wr[8 * t] =
            make_float4(sc[0] * inv, sc[1] * inv, sc[2] * inv, sc[3] * inv);
        *(float4*)&wr[8 * t + 4] =
            make_float4(sc[4] * inv, sc[5] * inv, sc[6] * inv, sc[7] * inv);
    }
    __syncwarp();

    // g[c] = sum_r w[r]*xf[c][r]; thread owns c = t, t+32
    {
        const float* wr = &wbf[w * 260];
        float a0 = 0.f, a1 = 0.f;
        #pragma unroll 4
        for (int q = 0; q < 32; q++) {
            float4 w0 = *(const float4*)&wr[8 * q];
            float4 w1 = *(const float4*)&wr[8 * q + 4];
            uint4 v0 = ((const uint4*)(xfs + t * RPADH))[q];
            uint4 v1 = ((const uint4*)(xfs + (t + 32) * RPADH))[q];
            float2 p;
            p = __bfloat1622float2(*(__nv_bfloat162*)&v0.x); a0 += w0.x * p.x + w0.y * p.y;
            p = __bfloat1622float2(*(__nv_bfloat162*)&v0.y); a0 += w0.z * p.x + w0.w * p.y;
            p = __bfloat1622float2(*(__nv_bfloat162*)&v0.z); a0 += w1.x * p.x + w1.y * p.y;
            p = __bfloat1622float2(*(__nv_bfloat162*)&v0.w); a0 += w1.z * p.x + w1.w * p.y;
            p = __bfloat1622float2(*(__nv_bfloat162*)&v1.x); a1 += w0.x * p.x + w0.y * p.y;
            p = __bfloat1622float2(*(__nv_bfloat162*)&v1.y); a1 += w0.z * p.x + w0.w * p.y;
            p = __bfloat1622float2(*(__nv_bfloat162*)&v1.z); a1 += w1.x * p.x + w1.y * p.y;
            p = __bfloat1622float2(*(__nv_bfloat162*)&v1.w); a1 += w1.z * p.x + w1.w * p.y;
        }
        g_gv[b * (LANES_ * CC) + lane * CC + t] = a0;
        g_gv[b * (LANES_ * CC) + lane * CC + t + 32] = a1;
    }
}

// ---------------- K4: conv1x1 + relu + broadcast-add prior ----------------
__global__ void final_kernel(const float* __restrict__ w1x1,
                             const float* __restrict__ b1x1,
                             const float* __restrict__ prior,
                             float* __restrict__ out) {
    int og = blockIdx.x;
    int b = blockIdx.y;
    int tid = threadIdx.x;
    int w = tid >> 5, t = tid & 31;

    __shared__ float gvs[4096];
    __shared__ float vals[8];
    for (int i = tid; i < 4096; i += 256) gvs[i] = g_gv[b * 4096 + i];
    __syncthreads();

    int o = og * 8 + w;
    const float* wrow = w1x1 + (size_t)o * 4096;
    float s = 0.f;
    for (int j = t * 4; j < 4096; j += 128) {
        float4 wv = *(const float4*)&wrow[j];
        float4 gv = *(const float4*)&gvs[j];
        s += wv.x * gv.x + wv.y * gv.y + wv.z * gv.z + wv.w * gv.w;
    }
    #pragma unroll
    for (int off = 16; off > 0; off >>= 1)
        s += __shfl_xor_sync(0xffffffffu, s, off);
    if (t == 0) vals[w] = fmaxf(s + b1x1[o], 0.f);
    __syncthreads();

    for (int i = tid; i < 8 * PE_; i += 256) {
        int oo = i / PE_, e = i % PE_;
        int oabs = og * 8 + oo;
        int idx = b * (CC * PE_) + oabs * PE_ + e;
        out[idx] = vals[oo] + prior[idx];
    }
}

// ---------------- launch ----------------
extern "C" void kernel_launch(void* const* d_in, const int* in_sizes, int n_in,
                              void* d_out, int out_size) {
    const float* feat    = (const float*)d_in[0];
    const float* prior   = (const float*)d_in[1];
    const float* conv_w  = (const float*)d_in[2];
    const float* conv_b  = (const float*)d_in[3];
    const float* fc_w    = (const float*)d_in[4];
    const float* fc_b    = (const float*)d_in[5];
    const float* w1x1    = (const float*)d_in[6];
    const float* b1x1    = (const float*)d_in[7];
    float* out = (float*)d_out;

    const int prep_smem = (FHH * FWW) * 4 + (SPP * LANES_) * 4 + 16;
    const int attn_smem = (CC * RPADH) * 2 + (8 * 260 + 8 * CC) * 4;
    cudaFuncSetAttribute(prep_kernel,
                         cudaFuncAttributeMaxDynamicSharedMemorySize, prep_smem);
    cudaFuncSetAttribute(attn_kernel,
                         cudaFuncAttributeMaxDynamicSharedMemorySize, attn_smem);

    prep_kernel<<<256 + CC * BB, 256, prep_smem>>>(feat, prior, conv_w, conv_b,
                                                   fc_w, fc_b);
    gemm_kernel<<<dim3(32, NSPLIT), 256>>>();
    attn_kernel<<<dim3(8, BB), 256, attn_smem>>>();
    final_kernel<<<dim3(8, BB), 256>>>(w1x1, b1x1, prior, out);
}